// round 10
// baseline (speedup 1.0000x reference)
#include <cuda_runtime.h>
#include <math.h>

#define BB 32
#define CC 512
#define TT 1024
#define KS 13
#define RAD 6
#define TILE_C 32
#define TILE_T 64
#define NTILES (TT / TILE_T)          // 16
#define NTHR 96                        // 2 producer warps + 1 consumer warp
#define NPROD 64
#define ROWS (TILE_C + 2 * RAD)       // 44
#define SROW 68                        // 64 + 4 pad (floats)
#define DROW 68
#define NBUF 2                         // IN ring
#define NDR 3                          // DR ring (drive+spikes)
#define THRV 0.5f
#define BETA 0.95f

#define IN_TILE (ROWS * SROW)         // 2992 floats
#define DR_TILE (TILE_C * DROW)       // 2176 floats
#define SMEM_FLOATS (NBUF * IN_TILE + NDR * DR_TILE)   // 12512 floats = 50048 B

typedef unsigned long long ull;

__device__ __forceinline__ void cp_async_16(unsigned saddr, const void* gptr, int src_sz) {
    asm volatile("cp.async.ca.shared.global [%0], [%1], 16, %2;\n"
                 :: "r"(saddr), "l"(gptr), "r"(src_sz));
}
__device__ __forceinline__ void cp_commit() {
    asm volatile("cp.async.commit_group;\n");
}
__device__ __forceinline__ void cp_wait1() {
    asm volatile("cp.async.wait_group 1;\n");
}
__device__ __forceinline__ void bar_prod() {      // named barrier: 2 producer warps
    asm volatile("bar.sync 1, 64;\n" ::: "memory");
}
// packed f32x2 FMA: two independent correctly-rounded fp32 FMAs (bit-exact per lane)
__device__ __forceinline__ void ffma2(ull& d, ull a, ull b) {
    asm("fma.rn.f32x2 %0, %1, %2, %0;" : "+l"(d) : "l"(a), "l"(b));
}
__device__ __forceinline__ ull pack2(float a) {
    ull r;
    asm("mov.b64 %0, {%1, %2};" : "=l"(r) : "f"(a), "f"(a));
    return r;
}
union V2 { ulonglong2 u; float4 f; };

// Producers cooperatively load ROWS x TILE_T tile (channel halo, zero-filled OOB).
// 44 rows * 16 quads = 704 float4 over 64 threads = 11 iterations.
__device__ __forceinline__ void load_tile(const float* __restrict__ xb,
                                          int c0, int t0, float* __restrict__ sbuf,
                                          int ptid) {
#pragma unroll
    for (int it = 0; it < 11; ++it) {
        int i = ptid + it * NPROD;     // 0..703
        int r = i >> 4;                // 0..43
        int g = i & 15;
        int ch = c0 + r - RAD;
        bool valid = ((unsigned)ch < (unsigned)CC);
        const float* gp = xb + (size_t)(valid ? ch : 0) * TT + t0 + g * 4;
        unsigned sa = (unsigned)__cvta_generic_to_shared(sbuf + r * SROW + g * 4);
        cp_async_16(sa, gp, valid ? 16 : 0);
    }
}

extern __shared__ float smem[];

__global__ void __launch_bounds__(NTHR, 4)
snn_ws10(const float* __restrict__ x,
         const float* __restrict__ wp,
         float* __restrict__ out) {
    const int tid = threadIdx.x;
    const bool producer = (tid < NPROD);
    const int ptid = tid;
    const int ctid = tid - NPROD;         // consumer channel within tile (0..31)
    const int c0 = blockIdx.x * TILE_C;
    const int b  = blockIdx.y;

    const float* xb = x + (size_t)b * CC * TT;

    float* IN = smem;                     // NBUF tiles of ROWS x SROW
    float* DR = smem + NBUF * IN_TILE;    // NDR tiles (drive, then spikes in-place)

    // ---- producer setup: symmetric Gaussian taps (values bit-identical to R1) ----
    ull kp[RAD + 1];
    int s = 0, g = 0;
    if (producer) {
        s = ptid >> 4;                    // strip (0..3): channels s*8..s*8+7
        g = ptid & 15;                    // float4 t-group (0..15)
        float wv = wp[0];
        float sigma = 0.5f * (1.0f + 10.0f) + fminf(fmaxf(wv, 1.0f), 10.0f);
        float inv2s2 = 0.5f / (sigma * sigma);
        float tmp[KS];
        float ksum = 0.0f;
#pragma unroll
        for (int j = 0; j < KS; ++j) {
            float r = (float)(j - RAD);
            tmp[j] = expf(-r * r * inv2s2);
            ksum += tmp[j];
        }
        float kinv = 1.0f / ksum;
#pragma unroll
        for (int j = 0; j <= RAD; ++j) kp[j] = pack2(tmp[j] * kinv);

        // prologue: tile 0 in flight
        load_tile(xb, c0, 0, IN, ptid);
        cp_commit();
    }

    float mem = 0.0f;                     // consumer LIF state
    float* outbase = out + (size_t)b * CC * TT + (size_t)c0 * TT;

    for (int i = 0; i < NTILES; ++i) {
        if (producer) {
            if (i + 1 < NTILES)
                load_tile(xb, c0, (i + 1) * TILE_T, IN + ((i + 1) & 1) * IN_TILE, ptid);
            cp_commit();
            cp_wait1();                   // tile i's data landed (1 newer group outstanding)
            bar_prod();

            // ---- strip-8 conv of tile i: rows s*8 .. s*8+19, outputs ch s*8+k ----
            const float* sb = IN + (i & 1) * IN_TILE + (s * 8) * SROW + g * 4;
            V2 acc[8];
#pragma unroll
            for (int k = 0; k < 8; ++k) { acc[k].u.x = 0ull; acc[k].u.y = 0ull; }
#pragma unroll
            for (int m = 0; m < 20; ++m) {
                V2 v;
                v.u = *(const ulonglong2*)(sb + m * SROW);
#pragma unroll
                for (int k = 0; k < 8; ++k) {
                    int j = m - k;
                    if (j >= 0 && j < KS) {
                        ull kj = kp[(j <= RAD) ? j : (KS - 1 - j)];   // symmetric taps
                        ffma2(acc[k].u.x, v.u.x, kj);
                        ffma2(acc[k].u.y, v.u.y, kj);
                    }
                }
            }
            float* dst = DR + (i % NDR) * DR_TILE + (s * 8) * DROW + g * 4;
#pragma unroll
            for (int k = 0; k < 8; ++k) {
                // re-load the center row (L1-hot smem) instead of keeping 32 regs live
                V2 vc;
                vc.u = *(const ulonglong2*)(sb + (k + RAD) * SROW);
                float4 d4;
                d4.x = vc.f.x - acc[k].f.x;
                d4.y = vc.f.y - acc[k].f.y;
                d4.z = vc.f.z - acc[k].f.z;
                d4.w = vc.f.w - acc[k].f.w;
                *(float4*)(dst + k * DROW) = d4;
            }
        }

        __syncthreads();    // publish DR[i%NDR]; ring distance guarantees no WAR on wb buffer

        if (!producer) {
            // ---- overlapped writeback of tile i-1 spikes (independent of scan chain) ----
            if (i >= 1) {
                const float* sp = DR + ((i - 1) % NDR) * DR_TILE;
#pragma unroll
                for (int it = 0; it < 16; ++it) {
                    int idx = ctid + it * 32;      // 0..511
                    int r  = idx >> 4;             // channel row 0..31
                    int gg = idx & 15;             // t-quad 0..15
                    float4 v = *(const float4*)(sp + r * DROW + gg * 4);
                    *(float4*)(outbase + (size_t)r * TT + (size_t)(i - 1) * TILE_T + gg * 4) = v;
                }
            }

            // ---- LIF scan tile i (bit-identical to R1); spikes written in-place ----
            float* dr = DR + (i % NDR) * DR_TILE + ctid * DROW;
#pragma unroll
            for (int gg = 0; gg < TILE_T / 4; ++gg) {
                float4 d4 = *(const float4*)(dr + gg * 4);
                float4 spk;
                mem = fmaf(BETA, mem, d4.x) - ((mem > THRV) ? THRV : 0.0f);
                spk.x = (mem > THRV) ? 1.0f : 0.0f;
                mem = fmaf(BETA, mem, d4.y) - ((mem > THRV) ? THRV : 0.0f);
                spk.y = (mem > THRV) ? 1.0f : 0.0f;
                mem = fmaf(BETA, mem, d4.z) - ((mem > THRV) ? THRV : 0.0f);
                spk.z = (mem > THRV) ? 1.0f : 0.0f;
                mem = fmaf(BETA, mem, d4.w) - ((mem > THRV) ? THRV : 0.0f);
                spk.w = (mem > THRV) ? 1.0f : 0.0f;
                *(float4*)(dr + gg * 4) = spk;
            }
            __syncwarp();
        }
    }

    // ---- final writeback: tile NTILES-1 spikes ----
    if (!producer) {
        const float* sp = DR + ((NTILES - 1) % NDR) * DR_TILE;
#pragma unroll
        for (int it = 0; it < 16; ++it) {
            int idx = ctid + it * 32;
            int r  = idx >> 4;
            int gg = idx & 15;
            float4 v = *(const float4*)(sp + r * DROW + gg * 4);
            *(float4*)(outbase + (size_t)r * TT + (size_t)(NTILES - 1) * TILE_T + gg * 4) = v;
        }
    }
}

extern "C" void kernel_launch(void* const* d_in, const int* in_sizes, int n_in,
                              void* d_out, int out_size) {
    const float* inp = (const float*)d_in[0];
    const float* wv  = (const float*)d_in[1];
    float* out       = (float*)d_out;

    cudaFuncSetAttribute(snn_ws10, cudaFuncAttributeMaxDynamicSharedMemorySize,
                         SMEM_FLOATS * 4);

    dim3 grid(CC / TILE_C, BB);   // (16, 32) = 512 CTAs
    dim3 blk(NTHR);               // 96 threads: 2 producer + 1 consumer warps
    snn_ws10<<<grid, blk, SMEM_FLOATS * 4>>>(inp, wv, out);
}

// round 11
// speedup vs baseline: 1.0092x; 1.0092x over previous
#include <cuda_runtime.h>
#include <math.h>

#define BB 32
#define CC 512
#define TT 1024
#define KS 13
#define RAD 6
#define TILE_C 32
#define TILE_T 64
#define NTILES (TT / TILE_T)          // 16
#define NTHR 96                        // 2 producer warps + 1 consumer warp
#define NPROD 64
#define ROWS (TILE_C + 2 * RAD)       // 44
#define SROW 68                        // 64 + 4 pad (floats)
#define DROW 68
#define NBUF 2                         // IN ring
#define NDR 3                          // DR ring (drive+spikes)
#define THRV 0.5f
#define BETA 0.95f

#define IN_TILE (ROWS * SROW)         // 2992 floats
#define DR_TILE (TILE_C * DROW)       // 2176 floats
#define SMEM_FLOATS (NBUF * IN_TILE + NDR * DR_TILE)   // 12512 floats = 50048 B

typedef unsigned long long ull;

__device__ __forceinline__ void cp_async_16(unsigned saddr, const void* gptr, int src_sz) {
    asm volatile("cp.async.ca.shared.global [%0], [%1], 16, %2;\n"
                 :: "r"(saddr), "l"(gptr), "r"(src_sz));
}
__device__ __forceinline__ void cp_commit() {
    asm volatile("cp.async.commit_group;\n");
}
__device__ __forceinline__ void cp_wait1() {
    asm volatile("cp.async.wait_group 1;\n");
}
__device__ __forceinline__ void bar_prod() {      // named barrier: 2 producer warps
    asm volatile("bar.sync 1, 64;\n" ::: "memory");
}
// packed f32x2 FMA: two independent correctly-rounded fp32 FMAs (bit-exact per lane)
__device__ __forceinline__ void ffma2(ull& d, ull a, ull b) {
    asm("fma.rn.f32x2 %0, %1, %2, %0;" : "+l"(d) : "l"(a), "l"(b));
}
__device__ __forceinline__ ull pack2(float a) {
    ull r;
    asm("mov.b64 %0, {%1, %2};" : "=l"(r) : "f"(a), "f"(a));
    return r;
}
union V2 { ulonglong2 u; float4 f; };

// Producers cooperatively load ROWS x TILE_T tile (channel halo, zero-filled OOB).
// 44 rows * 16 quads = 704 float4 over 64 threads = 11 iterations.
__device__ __forceinline__ void load_tile(const float* __restrict__ xb,
                                          int c0, int t0, float* __restrict__ sbuf,
                                          int ptid) {
#pragma unroll
    for (int it = 0; it < 11; ++it) {
        int i = ptid + it * NPROD;     // 0..703
        int r = i >> 4;                // 0..43
        int g = i & 15;
        int ch = c0 + r - RAD;
        bool valid = ((unsigned)ch < (unsigned)CC);
        const float* gp = xb + (size_t)(valid ? ch : 0) * TT + t0 + g * 4;
        unsigned sa = (unsigned)__cvta_generic_to_shared(sbuf + r * SROW + g * 4);
        cp_async_16(sa, gp, valid ? 16 : 0);
    }
}

extern __shared__ float smem[];

__global__ void __launch_bounds__(NTHR, 4)
snn_ws10(const float* __restrict__ x,
         const float* __restrict__ wp,
         float* __restrict__ out) {
    const int tid = threadIdx.x;
    const bool producer = (tid < NPROD);
    const int ptid = tid;
    const int ctid = tid - NPROD;         // consumer channel within tile (0..31)
    const int c0 = blockIdx.x * TILE_C;
    const int b  = blockIdx.y;

    const float* xb = x + (size_t)b * CC * TT;

    float* IN = smem;                     // NBUF tiles of ROWS x SROW
    float* DR = smem + NBUF * IN_TILE;    // NDR tiles (drive, then spikes in-place)

    // ---- producer setup: symmetric Gaussian taps (values bit-identical to R1) ----
    ull kp[RAD + 1];
    int s = 0, g = 0;
    if (producer) {
        s = ptid >> 4;                    // strip (0..3): channels s*8..s*8+7
        g = ptid & 15;                    // float4 t-group (0..15)
        float wv = wp[0];
        float sigma = 0.5f * (1.0f + 10.0f) + fminf(fmaxf(wv, 1.0f), 10.0f);
        float inv2s2 = 0.5f / (sigma * sigma);
        float tmp[KS];
        float ksum = 0.0f;
#pragma unroll
        for (int j = 0; j < KS; ++j) {
            float r = (float)(j - RAD);
            tmp[j] = expf(-r * r * inv2s2);
            ksum += tmp[j];
        }
        float kinv = 1.0f / ksum;
#pragma unroll
        for (int j = 0; j <= RAD; ++j) kp[j] = pack2(tmp[j] * kinv);

        // prologue: tile 0 in flight
        load_tile(xb, c0, 0, IN, ptid);
        cp_commit();
    }

    float mem = 0.0f;                     // consumer LIF state
    float* outbase = out + (size_t)b * CC * TT + (size_t)c0 * TT;

    for (int i = 0; i < NTILES; ++i) {
        if (producer) {
            if (i + 1 < NTILES)
                load_tile(xb, c0, (i + 1) * TILE_T, IN + ((i + 1) & 1) * IN_TILE, ptid);
            cp_commit();
            cp_wait1();                   // tile i's data landed (1 newer group outstanding)
            bar_prod();

            // ---- strip-8 conv of tile i: rows s*8 .. s*8+19, outputs ch s*8+k ----
            const float* sb = IN + (i & 1) * IN_TILE + (s * 8) * SROW + g * 4;
            V2 acc[8];
#pragma unroll
            for (int k = 0; k < 8; ++k) { acc[k].u.x = 0ull; acc[k].u.y = 0ull; }
#pragma unroll
            for (int m = 0; m < 20; ++m) {
                V2 v;
                v.u = *(const ulonglong2*)(sb + m * SROW);
#pragma unroll
                for (int k = 0; k < 8; ++k) {
                    int j = m - k;
                    if (j >= 0 && j < KS) {
                        ull kj = kp[(j <= RAD) ? j : (KS - 1 - j)];   // symmetric taps
                        ffma2(acc[k].u.x, v.u.x, kj);
                        ffma2(acc[k].u.y, v.u.y, kj);
                    }
                }
            }
            float* dst = DR + (i % NDR) * DR_TILE + (s * 8) * DROW + g * 4;
#pragma unroll
            for (int k = 0; k < 8; ++k) {
                // re-load the center row (L1-hot smem) instead of keeping 32 regs live
                V2 vc;
                vc.u = *(const ulonglong2*)(sb + (k + RAD) * SROW);
                float4 d4;
                d4.x = vc.f.x - acc[k].f.x;
                d4.y = vc.f.y - acc[k].f.y;
                d4.z = vc.f.z - acc[k].f.z;
                d4.w = vc.f.w - acc[k].f.w;
                *(float4*)(dst + k * DROW) = d4;
            }
        }

        __syncthreads();    // publish DR[i%NDR]; ring distance guarantees no WAR on wb buffer

        if (!producer) {
            // ---- overlapped writeback of tile i-1 spikes (independent of scan chain) ----
            if (i >= 1) {
                const float* sp = DR + ((i - 1) % NDR) * DR_TILE;
#pragma unroll
                for (int it = 0; it < 16; ++it) {
                    int idx = ctid + it * 32;      // 0..511
                    int r  = idx >> 4;             // channel row 0..31
                    int gg = idx & 15;             // t-quad 0..15
                    float4 v = *(const float4*)(sp + r * DROW + gg * 4);
                    *(float4*)(outbase + (size_t)r * TT + (size_t)(i - 1) * TILE_T + gg * 4) = v;
                }
            }

            // ---- LIF scan tile i (bit-identical to R1); spikes written in-place ----
            float* dr = DR + (i % NDR) * DR_TILE + ctid * DROW;
#pragma unroll
            for (int gg = 0; gg < TILE_T / 4; ++gg) {
                float4 d4 = *(const float4*)(dr + gg * 4);
                float4 spk;
                mem = fmaf(BETA, mem, d4.x) - ((mem > THRV) ? THRV : 0.0f);
                spk.x = (mem > THRV) ? 1.0f : 0.0f;
                mem = fmaf(BETA, mem, d4.y) - ((mem > THRV) ? THRV : 0.0f);
                spk.y = (mem > THRV) ? 1.0f : 0.0f;
                mem = fmaf(BETA, mem, d4.z) - ((mem > THRV) ? THRV : 0.0f);
                spk.z = (mem > THRV) ? 1.0f : 0.0f;
                mem = fmaf(BETA, mem, d4.w) - ((mem > THRV) ? THRV : 0.0f);
                spk.w = (mem > THRV) ? 1.0f : 0.0f;
                *(float4*)(dr + gg * 4) = spk;
            }
            __syncwarp();
        }
    }

    // ---- final writeback: tile NTILES-1 spikes ----
    if (!producer) {
        const float* sp = DR + ((NTILES - 1) % NDR) * DR_TILE;
#pragma unroll
        for (int it = 0; it < 16; ++it) {
            int idx = ctid + it * 32;
            int r  = idx >> 4;
            int gg = idx & 15;
            float4 v = *(const float4*)(sp + r * DROW + gg * 4);
            *(float4*)(outbase + (size_t)r * TT + (size_t)(NTILES - 1) * TILE_T + gg * 4) = v;
        }
    }
}

extern "C" void kernel_launch(void* const* d_in, const int* in_sizes, int n_in,
                              void* d_out, int out_size) {
    const float* inp = (const float*)d_in[0];
    const float* wv  = (const float*)d_in[1];
    float* out       = (float*)d_out;

    cudaFuncSetAttribute(snn_ws10, cudaFuncAttributeMaxDynamicSharedMemorySize,
                         SMEM_FLOATS * 4);

    dim3 grid(CC / TILE_C, BB);   // (16, 32) = 512 CTAs
    dim3 blk(NTHR);               // 96 threads: 2 producer + 1 consumer warps
    snn_ws10<<<grid, blk, SMEM_FLOATS * 4>>>(inp, wv, out);
}

// round 15
// speedup vs baseline: 1.0252x; 1.0159x over previous
#include <cuda_runtime.h>
#include <math.h>

#define BB 32
#define CC 512
#define TT 1024
#define KS 13
#define RAD 6
#define TILE_C 32
#define TILE_T 64
#define NTILES (TT / TILE_T)          // 16
#define NTHR 128                       // w0,w1: conv+load, w2: load, w3: consumer
#define NPROD 96
#define NCONV 64
#define ROWS (TILE_C + 2 * RAD)       // 44
#define SROW 68
#define DROW 68
#define NBUF 2                         // IN ring
#define NDR 3                          // DR ring
#define THRV 0.5f
#define BETA 0.95f

#define IN_TILE (ROWS * SROW)         // 2992 floats
#define DR_TILE (TILE_C * DROW)       // 2176 floats
#define SMEM_FLOATS (NBUF * IN_TILE + NDR * DR_TILE)   // 12512 floats = 50048 B

typedef unsigned long long ull;

__device__ __forceinline__ void cp_async_16(unsigned saddr, const void* gptr, int src_sz) {
    asm volatile("cp.async.ca.shared.global [%0], [%1], 16, %2;\n"
                 :: "r"(saddr), "l"(gptr), "r"(src_sz));
}
__device__ __forceinline__ void cp_commit() {
    asm volatile("cp.async.commit_group;\n");
}
__device__ __forceinline__ void cp_wait1() {
    asm volatile("cp.async.wait_group 1;\n");
}
// producer barriers (96 threads each)
__device__ __forceinline__ void bar_sync_n(int id) {
    asm volatile("bar.sync %0, 96;\n" :: "r"(id) : "memory");
}
// full[k]/empty[k] pairs: 64 conv + 32 consumer = 96 participants
__device__ __forceinline__ void bar_arrive96(int id) {
    asm volatile("bar.arrive %0, 96;\n" :: "r"(id) : "memory");
}
__device__ __forceinline__ void ffma2(ull& d, ull a, ull b) {
    asm("fma.rn.f32x2 %0, %1, %2, %0;" : "+l"(d) : "l"(a), "l"(b));
}
__device__ __forceinline__ ull pack2(float a) {
    ull r;
    asm("mov.b64 %0, {%1, %2};" : "=l"(r) : "f"(a), "f"(a));
    return r;
}
union V2 { ulonglong2 u; float4 f; };

// 44 rows * 16 quads = 704 float4 over 96 threads (8 strided iterations).
__device__ __forceinline__ void load_tile(const float* __restrict__ xb,
                                          int c0, int t0, float* __restrict__ sbuf,
                                          int ptid) {
#pragma unroll
    for (int it = 0; it < 8; ++it) {
        int i = ptid + it * NPROD;     // 0..767
        if (i < ROWS * (TILE_T / 4)) {
            int r = i >> 4;            // 0..43
            int g = i & 15;
            int ch = c0 + r - RAD;
            bool valid = ((unsigned)ch < (unsigned)CC);
            const float* gp = xb + (size_t)(valid ? ch : 0) * TT + t0 + g * 4;
            unsigned sa = (unsigned)__cvta_generic_to_shared(sbuf + r * SROW + g * 4);
            cp_async_16(sa, gp, valid ? 16 : 0);
        }
    }
}

extern __shared__ float smem[];

__global__ void __launch_bounds__(NTHR, 4)
snn_ws12(const float* __restrict__ x,
         const float* __restrict__ wp,
         float* __restrict__ out) {
    const int tid = threadIdx.x;
    const bool producer = (tid < NPROD);
    const bool convth   = (tid < NCONV);
    const int ctid = tid - NPROD;         // consumer channel (0..31)
    const int c0 = blockIdx.x * TILE_C;
    const int b  = blockIdx.y;

    const float* xb = x + (size_t)b * CC * TT;

    float* IN = smem;                     // NBUF tiles
    float* DR = smem + NBUF * IN_TILE;    // NDR tiles (drive -> spikes in place)

    // ---- conv-thread setup: symmetric Gaussian taps (bit-identical values) ----
    ull kp[RAD + 1];
    int s = 0, g = 0;
    if (convth) {
        s = tid >> 4;                     // strip (0..3): channels s*8..s*8+7
        g = tid & 15;                     // t-quad (0..15)
        float wv = wp[0];
        float sigma = 0.5f * (1.0f + 10.0f) + fminf(fmaxf(wv, 1.0f), 10.0f);
        float inv2s2 = 0.5f / (sigma * sigma);
        float tmp[KS];
        float ksum = 0.0f;
#pragma unroll
        for (int j = 0; j < KS; ++j) {
            float r = (float)(j - RAD);
            tmp[j] = expf(-r * r * inv2s2);
            ksum += tmp[j];
        }
        float kinv = 1.0f / ksum;
#pragma unroll
        for (int j = 0; j <= RAD; ++j) kp[j] = pack2(tmp[j] * kinv);
    }

    if (producer) {
        // prologue: tile 0 in flight
        load_tile(xb, c0, 0, IN, tid);
        cp_commit();

        for (int i = 0; i < NTILES; ++i) {
            bar_sync_n(1);                // conv(i-1) done by all -> IN[(i+1)&1] free
            if (i + 1 < NTILES)
                load_tile(xb, c0, (i + 1) * TILE_T, IN + ((i + 1) & 1) * IN_TILE, tid);
            cp_commit();
            cp_wait1();                   // my slices of IN[i] landed
            bar_sync_n(8);                // everyone's slices of IN[i] visible

            if (convth) {
                if (i >= NDR)
                    asm volatile("bar.sync %0, 96;\n" :: "r"(5 + i % NDR) : "memory"); // empty[k]

                // ---- strip-8 conv of tile i (R8-exact) ----
                const float* sb = IN + (i & 1) * IN_TILE + (s * 8) * SROW + g * 4;
                V2 acc[8];
#pragma unroll
                for (int k = 0; k < 8; ++k) { acc[k].u.x = 0ull; acc[k].u.y = 0ull; }
#pragma unroll
                for (int m = 0; m < 20; ++m) {
                    V2 v;
                    v.u = *(const ulonglong2*)(sb + m * SROW);
#pragma unroll
                    for (int k = 0; k < 8; ++k) {
                        int j = m - k;
                        if (j >= 0 && j < KS) {
                            ull kj = kp[(j <= RAD) ? j : (KS - 1 - j)];
                            ffma2(acc[k].u.x, v.u.x, kj);
                            ffma2(acc[k].u.y, v.u.y, kj);
                        }
                    }
                }
                float* dst = DR + (i % NDR) * DR_TILE + (s * 8) * DROW + g * 4;
#pragma unroll
                for (int k = 0; k < 8; ++k) {
                    V2 vc;
                    vc.u = *(const ulonglong2*)(sb + (k + RAD) * SROW);
                    float4 d4;
                    d4.x = vc.f.x - acc[k].f.x;
                    d4.y = vc.f.y - acc[k].f.y;
                    d4.z = vc.f.z - acc[k].f.z;
                    d4.w = vc.f.w - acc[k].f.w;
                    *(float4*)(dst + k * DROW) = d4;
                }
                bar_arrive96(2 + i % NDR);    // full[k]: DR[i%NDR] published
            }
        }
    } else if (ctid >= 0 && ctid < 32) {
        // ================= consumer warp =================
        float mem = 0.0f, spk = 0.0f;
        float* outbase = out + (size_t)b * CC * TT + (size_t)c0 * TT;

        for (int i = 0; i < NTILES; ++i) {
            asm volatile("bar.sync %0, 96;\n" :: "r"(2 + i % NDR) : "memory");  // full[k]

            // ---- overlapped writeback of tile i-1 spikes ----
            if (i >= 1) {
                const float* sp = DR + ((i - 1) % NDR) * DR_TILE;
#pragma unroll
                for (int it = 0; it < 16; ++it) {
                    int idx = ctid + it * 32;
                    int r  = idx >> 4;
                    int gg = idx & 15;
                    float4 v = *(const float4*)(sp + r * DROW + gg * 4);
                    *(float4*)(outbase + (size_t)r * TT + (size_t)(i - 1) * TILE_T + gg * 4) = v;
                }
            }

            // ---- LIF scan tile i: 12-cyc/step chain, bit-exact spikes ----
            float* dr = DR + (i % NDR) * DR_TILE + ctid * DROW;
#pragma unroll
            for (int gg = 0; gg < TILE_T / 4; ++gg) {
                float4 d4 = *(const float4*)(dr + gg * 4);
                float4 sv;
                float t;
                t = fmaf(BETA, mem, d4.x);  mem = fmaf(-THRV, spk, t);
                spk = __saturatef((mem - THRV) * 1e38f);  sv.x = spk;
                t = fmaf(BETA, mem, d4.y);  mem = fmaf(-THRV, spk, t);
                spk = __saturatef((mem - THRV) * 1e38f);  sv.y = spk;
                t = fmaf(BETA, mem, d4.z);  mem = fmaf(-THRV, spk, t);
                spk = __saturatef((mem - THRV) * 1e38f);  sv.z = spk;
                t = fmaf(BETA, mem, d4.w);  mem = fmaf(-THRV, spk, t);
                spk = __saturatef((mem - THRV) * 1e38f);  sv.w = spk;
                *(float4*)(dr + gg * 4) = sv;
            }
            __syncwarp();

            if (i >= 1)
                bar_arrive96(5 + (i - 1) % NDR);   // empty[(i-1)%NDR]: slot fully consumed
        }

        // final writeback: tile NTILES-1
        {
            const float* sp = DR + ((NTILES - 1) % NDR) * DR_TILE;
#pragma unroll
            for (int it = 0; it < 16; ++it) {
                int idx = ctid + it * 32;
                int r  = idx >> 4;
                int gg = idx & 15;
                float4 v = *(const float4*)(sp + r * DROW + gg * 4);
                *(float4*)(outbase + (size_t)r * TT + (size_t)(NTILES - 1) * TILE_T + gg * 4) = v;
            }
        }
    }
}

extern "C" void kernel_launch(void* const* d_in, const int* in_sizes, int n_in,
                              void* d_out, int out_size) {
    const float* inp = (const float*)d_in[0];
    const float* wv  = (const float*)d_in[1];
    float* out       = (float*)d_out;

    cudaFuncSetAttribute(snn_ws12, cudaFuncAttributeMaxDynamicSharedMemorySize,
                         SMEM_FLOATS * 4);

    dim3 grid(CC / TILE_C, BB);   // (16, 32) = 512 CTAs
    dim3 blk(NTHR);               // 128 threads / 4 warps -> all SMSPs fed
    snn_ws12<<<grid, blk, SMEM_FLOATS * 4>>>(inp, wv, out);
}

// round 16
// speedup vs baseline: 1.1249x; 1.0972x over previous
#include <cuda_runtime.h>
#include <math.h>

#define BB 32
#define CC 512
#define TT 1024
#define KS 13
#define RAD 6
#define TILE_C 32
#define TILE_T 64
#define NTILES (TT / TILE_T)          // 16
#define NTHR 128                       // w0,w1 conv | w2 loader+writeback | w3 consumer
#define NCONV 64
#define ROWS (TILE_C + 2 * RAD)       // 44
#define SROW 68
#define DROW 68
#define NBUF 2                         // IN ring
#define NDR 3                          // DR ring
#define THRV 0.5f
#define BETA 0.95f

#define IN_TILE (ROWS * SROW)         // 2992 floats
#define DR_TILE (TILE_C * DROW)       // 2176 floats
#define SMEM_FLOATS (NBUF * IN_TILE + NDR * DR_TILE)   // 12512 floats = 50048 B

// named barrier ids
#define BAR_FULL(k)    (1 + (k))      // 64 conv arrive + 32 consumer sync  (96)
#define BAR_SPK(k)     (4 + (k))      // 32 consumer arrive + 32 loader sync (64)
#define BAR_EMPTY(k)   (7 + (k))      // 32 loader arrive + 64 conv sync    (96)
#define BAR_INREADY(k) (10 + (k))     // 32 loader arrive + 64 conv sync    (96)
#define BAR_INFREE(k)  (12 + (k))     // 64 conv arrive + 32 loader sync    (96)

typedef unsigned long long ull;

__device__ __forceinline__ void cp_async_16(unsigned saddr, const void* gptr, int src_sz) {
    asm volatile("cp.async.ca.shared.global [%0], [%1], 16, %2;\n"
                 :: "r"(saddr), "l"(gptr), "r"(src_sz));
}
__device__ __forceinline__ void cp_commit() {
    asm volatile("cp.async.commit_group;\n");
}
__device__ __forceinline__ void cp_wait1() {
    asm volatile("cp.async.wait_group 1;\n");
}
__device__ __forceinline__ void bsync(int id, int n) {
    asm volatile("bar.sync %0, %1;\n" :: "r"(id), "r"(n) : "memory");
}
__device__ __forceinline__ void barrive(int id, int n) {
    asm volatile("bar.arrive %0, %1;\n" :: "r"(id), "r"(n) : "memory");
}
__device__ __forceinline__ void ffma2(ull& d, ull a, ull b) {
    asm("fma.rn.f32x2 %0, %1, %2, %0;" : "+l"(d) : "l"(a), "l"(b));
}
__device__ __forceinline__ ull pack2(float a) {
    ull r;
    asm("mov.b64 %0, {%1, %2};" : "=l"(r) : "f"(a), "f"(a));
    return r;
}
union V2 { ulonglong2 u; float4 f; };

extern __shared__ float smem[];

// Loader warp (32 threads): 44 rows * 16 quads = 704 float4 = 22 per thread.
__device__ __forceinline__ void load_tile32(const float* __restrict__ xb,
                                            int c0, int t0, float* __restrict__ sbuf,
                                            int lane) {
#pragma unroll
    for (int it = 0; it < 22; ++it) {
        int i = lane + it * 32;        // 0..703
        int r = i >> 4;                // 0..43
        int g = i & 15;
        int ch = c0 + r - RAD;
        bool valid = ((unsigned)ch < (unsigned)CC);
        const float* gp = xb + (size_t)(valid ? ch : 0) * TT + t0 + g * 4;
        unsigned sa = (unsigned)__cvta_generic_to_shared(sbuf + r * SROW + g * 4);
        cp_async_16(sa, gp, valid ? 16 : 0);
    }
}

__global__ void __launch_bounds__(NTHR, 4)
snn_ws16(const float* __restrict__ x,
         const float* __restrict__ wp,
         float* __restrict__ out) {
    const int tid  = threadIdx.x;
    const int wid  = tid >> 5;
    const int lane = tid & 31;
    const int c0 = blockIdx.x * TILE_C;
    const int b  = blockIdx.y;

    const float* xb = x + (size_t)b * CC * TT;
    float* outbase  = out + (size_t)b * CC * TT + (size_t)c0 * TT;

    float* IN = smem;                     // NBUF tiles
    float* DR = smem + NBUF * IN_TILE;    // NDR tiles (drive -> spikes in place)

    if (tid < NCONV) {
        // ================= conv warps (w0,w1) =================
        const int s = tid >> 4;           // strip 0..3: channels s*8..s*8+7
        const int g = tid & 15;           // t-quad 0..15
        float wv = wp[0];
        float sigma = 0.5f * (1.0f + 10.0f) + fminf(fmaxf(wv, 1.0f), 10.0f);
        float inv2s2 = 0.5f / (sigma * sigma);
        float tmp[KS];
        float ksum = 0.0f;
#pragma unroll
        for (int j = 0; j < KS; ++j) {
            float r = (float)(j - RAD);
            tmp[j] = expf(-r * r * inv2s2);
            ksum += tmp[j];
        }
        float kinv = 1.0f / ksum;
        ull kp[RAD + 1];
#pragma unroll
        for (int j = 0; j <= RAD; ++j) kp[j] = pack2(tmp[j] * kinv);

        for (int i = 0; i < NTILES; ++i) {
            bsync(BAR_INREADY(i & 1), 96);          // IN[i] visible
            if (i >= NDR) bsync(BAR_EMPTY(i % NDR), 96);  // DR slot recycled

            const float* sb = IN + (i & 1) * IN_TILE + (s * 8) * SROW + g * 4;
            V2 acc[8];
#pragma unroll
            for (int k = 0; k < 8; ++k) { acc[k].u.x = 0ull; acc[k].u.y = 0ull; }
#pragma unroll
            for (int m = 0; m < 20; ++m) {
                V2 v;
                v.u = *(const ulonglong2*)(sb + m * SROW);
#pragma unroll
                for (int k = 0; k < 8; ++k) {
                    int j = m - k;
                    if (j >= 0 && j < KS) {
                        ull kj = kp[(j <= RAD) ? j : (KS - 1 - j)];   // symmetric taps
                        ffma2(acc[k].u.x, v.u.x, kj);
                        ffma2(acc[k].u.y, v.u.y, kj);
                    }
                }
            }
            float* dst = DR + (i % NDR) * DR_TILE + (s * 8) * DROW + g * 4;
#pragma unroll
            for (int k = 0; k < 8; ++k) {
                V2 vc;
                vc.u = *(const ulonglong2*)(sb + (k + RAD) * SROW);
                float4 d4;
                d4.x = vc.f.x - acc[k].f.x;
                d4.y = vc.f.y - acc[k].f.y;
                d4.z = vc.f.z - acc[k].f.z;
                d4.w = vc.f.w - acc[k].f.w;
                *(float4*)(dst + k * DROW) = d4;
            }
            barrive(BAR_FULL(i % NDR), 96);         // drive published
            barrive(BAR_INFREE(i & 1), 96);         // done reading IN[i]
        }
    } else if (wid == 2) {
        // ================= loader + writeback warp =================
        load_tile32(xb, c0, 0, IN, lane);           // prologue: tile 0
        cp_commit();

        for (int i = 0; i < NTILES; ++i) {
            if (i >= 1 && i + 1 < NTILES)
                bsync(BAR_INFREE((i + 1) & 1), 96); // conv(i-1) released IN[(i+1)&1]
            if (i + 1 < NTILES)
                load_tile32(xb, c0, (i + 1) * TILE_T, IN + ((i + 1) & 1) * IN_TILE, lane);
            cp_commit();                            // commit every iter (uniform count)
            cp_wait1();                             // IN[i] landed
            barrive(BAR_INREADY(i & 1), 96);

            if (i >= 2) {
                int t = i - 2;
                bsync(BAR_SPK(t % NDR), 64);        // spikes of tile t ready
                const float* sp = DR + (t % NDR) * DR_TILE;
#pragma unroll
                for (int it = 0; it < 16; ++it) {
                    int idx = lane + it * 32;       // 0..511
                    int r  = idx >> 4;
                    int gg = idx & 15;
                    float4 v = *(const float4*)(sp + r * DROW + gg * 4);
                    *(float4*)(outbase + (size_t)r * TT + (size_t)t * TILE_T + gg * 4) = v;
                }
                barrive(BAR_EMPTY(t % NDR), 96);    // slot free for conv(t+3)
            }
        }
        // final writebacks: tiles NTILES-2, NTILES-1 (no empty arrive needed)
#pragma unroll
        for (int t = NTILES - 2; t < NTILES; ++t) {
            bsync(BAR_SPK(t % NDR), 64);
            const float* sp = DR + (t % NDR) * DR_TILE;
#pragma unroll
            for (int it = 0; it < 16; ++it) {
                int idx = lane + it * 32;
                int r  = idx >> 4;
                int gg = idx & 15;
                float4 v = *(const float4*)(sp + r * DROW + gg * 4);
                *(float4*)(outbase + (size_t)r * TT + (size_t)t * TILE_T + gg * 4) = v;
            }
        }
    } else if (wid == 3) {
        // ================= consumer warp: pure LIF scan =================
        float mem = 0.0f, spk = 0.0f;
        for (int i = 0; i < NTILES; ++i) {
            bsync(BAR_FULL(i % NDR), 96);           // drive ready
            float* dr = DR + (i % NDR) * DR_TILE + lane * DROW;
#pragma unroll
            for (int gg = 0; gg < TILE_T / 4; ++gg) {
                float4 d4 = *(const float4*)(dr + gg * 4);
                float4 sv;
                float t;
                t = fmaf(BETA, mem, d4.x);  mem = fmaf(-THRV, spk, t);
                spk = __saturatef((mem - THRV) * 1e38f);  sv.x = spk;
                t = fmaf(BETA, mem, d4.y);  mem = fmaf(-THRV, spk, t);
                spk = __saturatef((mem - THRV) * 1e38f);  sv.y = spk;
                t = fmaf(BETA, mem, d4.z);  mem = fmaf(-THRV, spk, t);
                spk = __saturatef((mem - THRV) * 1e38f);  sv.z = spk;
                t = fmaf(BETA, mem, d4.w);  mem = fmaf(-THRV, spk, t);
                spk = __saturatef((mem - THRV) * 1e38f);  sv.w = spk;
                *(float4*)(dr + gg * 4) = sv;
            }
            barrive(BAR_SPK(i % NDR), 64);          // spikes published for loader
        }
    }
}

extern "C" void kernel_launch(void* const* d_in, const int* in_sizes, int n_in,
                              void* d_out, int out_size) {
    const float* inp = (const float*)d_in[0];
    const float* wv  = (const float*)d_in[1];
    float* out       = (float*)d_out;

    cudaFuncSetAttribute(snn_ws16, cudaFuncAttributeMaxDynamicSharedMemorySize,
                         SMEM_FLOATS * 4);

    dim3 grid(CC / TILE_C, BB);   // (16, 32) = 512 CTAs
    dim3 blk(NTHR);               // 4 warps, one role per SMSP
    snn_ws16<<<grid, blk, SMEM_FLOATS * 4>>>(inp, wv, out);
}

// round 17
// speedup vs baseline: 1.3856x; 1.2317x over previous
#include <cuda_runtime.h>
#include <math.h>

#define BB 32
#define CC 512
#define TT 1024
#define KS 13
#define RAD 6
#define WCH 16                         // channels per warp
#define TILE_T 64
#define NTILES (TT / TILE_T)          // 16
#define NW 4                           // warps per CTA
#define NTHR (NW * 32)                // 128
#define ROWS (WCH + 2 * RAD)          // 28
#define SROW 68                        // 64 + 4 pad floats (16B-aligned rows)
#define NBUF 2
#define THRV 0.5f
#define BETA 0.95f

#define IN_TILE (ROWS * SROW)         // 1904 floats
#define DR_TILE (WCH * SROW)          // 1088 floats
#define WARP_FLOATS (NBUF * IN_TILE + DR_TILE)   // 4896 floats = 19584 B
#define SMEM_FLOATS (NW * WARP_FLOATS)           // 19584 floats = 78336 B

typedef unsigned long long ull;

__device__ __forceinline__ void cp_async_16(unsigned saddr, const void* gptr, int src_sz) {
    asm volatile("cp.async.ca.shared.global [%0], [%1], 16, %2;\n"
                 :: "r"(saddr), "l"(gptr), "r"(src_sz));
}
__device__ __forceinline__ void cp_commit() {
    asm volatile("cp.async.commit_group;\n");
}
__device__ __forceinline__ void cp_wait1() {
    asm volatile("cp.async.wait_group 1;\n");
}
__device__ __forceinline__ void ffma2(ull& d, ull a, ull b) {
    asm("fma.rn.f32x2 %0, %1, %2, %0;" : "+l"(d) : "l"(a), "l"(b));
}
__device__ __forceinline__ ull pack2(float a) {
    ull r;
    asm("mov.b64 %0, {%1, %2};" : "=l"(r) : "f"(a), "f"(a));
    return r;
}
union V2 { ulonglong2 u; float4 f; };

extern __shared__ float smem[];

// Per-warp load: ROWS x TILE_T tile (channel halo, zero-filled OOB).
// 28 rows * 16 quads = 448 float4 = 14 per lane.
__device__ __forceinline__ void load_tile(const float* __restrict__ xb,
                                          int cw, int t0, float* __restrict__ sbuf,
                                          int lane) {
#pragma unroll
    for (int it = 0; it < 14; ++it) {
        int i = lane + it * 32;        // 0..447
        int r = i >> 4;                // 0..27
        int g = i & 15;
        int ch = cw + r - RAD;
        bool valid = ((unsigned)ch < (unsigned)CC);
        const float* gp = xb + (size_t)(valid ? ch : 0) * TT + t0 + g * 4;
        unsigned sa = (unsigned)__cvta_generic_to_shared(sbuf + r * SROW + g * 4);
        cp_async_16(sa, gp, valid ? 16 : 0);
    }
}

__global__ void __launch_bounds__(NTHR, 2)
snn_fused17(const float* __restrict__ x,
            const float* __restrict__ wp,
            float* __restrict__ out) {
    const int tid  = threadIdx.x;
    const int wid  = tid >> 5;
    const int lane = tid & 31;
    const int cw   = blockIdx.x * (NW * WCH) + wid * WCH;   // warp's first channel
    const int b    = blockIdx.y;

    const float* xb = x + (size_t)b * CC * TT;
    float* outw     = out + (size_t)b * CC * TT + (size_t)cw * TT;

    float* W  = smem + wid * WARP_FLOATS;
    float* IN = W;                          // 2 tiles
    float* DR = W + NBUF * IN_TILE;         // 1 tile (drive -> spikes in place)

    // ---- symmetric Gaussian taps (bit-identical values to R1) ----
    float wv = wp[0];
    float sigma = 0.5f * (1.0f + 10.0f) + fminf(fmaxf(wv, 1.0f), 10.0f);
    float inv2s2 = 0.5f / (sigma * sigma);
    float tmp[KS];
    float ksum = 0.0f;
#pragma unroll
    for (int j = 0; j < KS; ++j) {
        float r = (float)(j - RAD);
        tmp[j] = expf(-r * r * inv2s2);
        ksum += tmp[j];
    }
    float kinv = 1.0f / ksum;
    ull kp[RAD + 1];
#pragma unroll
    for (int j = 0; j <= RAD; ++j) kp[j] = pack2(tmp[j] * kinv);

    const int s = lane >> 4;                // strip 0..1: channels s*8..s*8+7
    const int g = lane & 15;                // t-quad 0..15

    // prologue: tile 0 in flight
    load_tile(xb, cw, 0, IN, lane);
    cp_commit();

    float mem = 0.0f, spk = 0.0f;

    for (int i = 0; i < NTILES; ++i) {
        if (i + 1 < NTILES)
            load_tile(xb, cw, (i + 1) * TILE_T, IN + ((i + 1) & 1) * IN_TILE, lane);
        cp_commit();                        // uniform group count
        cp_wait1();                         // tile i landed (1 newer outstanding)
        __syncwarp();                       // all lanes' slices + prev wb reads done

        // ---- strip-8 conv of tile i (R8-exact ordering) ----
        const float* sb = IN + (i & 1) * IN_TILE + (s * 8) * SROW + g * 4;
        V2 acc[8];
#pragma unroll
        for (int k = 0; k < 8; ++k) { acc[k].u.x = 0ull; acc[k].u.y = 0ull; }
#pragma unroll
        for (int m = 0; m < 20; ++m) {
            V2 v;
            v.u = *(const ulonglong2*)(sb + m * SROW);
#pragma unroll
            for (int k = 0; k < 8; ++k) {
                int j = m - k;
                if (j >= 0 && j < KS) {
                    ull kj = kp[(j <= RAD) ? j : (KS - 1 - j)];   // symmetric taps
                    ffma2(acc[k].u.x, v.u.x, kj);
                    ffma2(acc[k].u.y, v.u.y, kj);
                }
            }
        }
        float* dst = DR + (s * 8) * SROW + g * 4;
#pragma unroll
        for (int k = 0; k < 8; ++k) {
            V2 vc;
            vc.u = *(const ulonglong2*)(sb + (k + RAD) * SROW);
            float4 d4;
            d4.x = vc.f.x - acc[k].f.x;
            d4.y = vc.f.y - acc[k].f.y;
            d4.z = vc.f.z - acc[k].f.z;
            d4.w = vc.f.w - acc[k].f.w;
            *(float4*)(dst + k * SROW) = d4;
        }
        __syncwarp();                       // drive visible to scan lanes

        // ---- LIF scan (lanes 0..15; 12-cyc/step chain, R16-exact) ----
        if (lane < WCH) {
            float* dr = DR + lane * SROW;
#pragma unroll
            for (int gg = 0; gg < TILE_T / 4; ++gg) {
                float4 d4 = *(const float4*)(dr + gg * 4);
                float4 sv;
                float t;
                t = fmaf(BETA, mem, d4.x);  mem = fmaf(-THRV, spk, t);
                spk = __saturatef((mem - THRV) * 1e38f);  sv.x = spk;
                t = fmaf(BETA, mem, d4.y);  mem = fmaf(-THRV, spk, t);
                spk = __saturatef((mem - THRV) * 1e38f);  sv.y = spk;
                t = fmaf(BETA, mem, d4.z);  mem = fmaf(-THRV, spk, t);
                spk = __saturatef((mem - THRV) * 1e38f);  sv.z = spk;
                t = fmaf(BETA, mem, d4.w);  mem = fmaf(-THRV, spk, t);
                spk = __saturatef((mem - THRV) * 1e38f);  sv.w = spk;
                *(float4*)(dr + gg * 4) = sv;
            }
        }
        __syncwarp();                       // spikes visible to all lanes

        // ---- coalesced writeback: 16 rows x 16 quads, lanes along t ----
#pragma unroll
        for (int it = 0; it < 8; ++it) {
            int idx = lane + it * 32;       // 0..255
            int r  = idx >> 4;              // channel row 0..15
            int gg = idx & 15;              // t-quad
            float4 v = *(const float4*)(DR + r * SROW + gg * 4);
            *(float4*)(outw + (size_t)r * TT + (size_t)i * TILE_T + gg * 4) = v;
        }
        __syncwarp();                       // wb reads done before next conv STS
    }
}

extern "C" void kernel_launch(void* const* d_in, const int* in_sizes, int n_in,
                              void* d_out, int out_size) {
    const float* inp = (const float*)d_in[0];
    const float* wv  = (const float*)d_in[1];
    float* out       = (float*)d_out;

    cudaFuncSetAttribute(snn_fused17, cudaFuncAttributeMaxDynamicSharedMemorySize,
                         SMEM_FLOATS * 4);

    dim3 grid(CC / (NW * WCH), BB);   // (8, 32) = 256 CTAs, 1024 independent warps
    dim3 blk(NTHR);
    snn_fused17<<<grid, blk, SMEM_FLOATS * 4>>>(inp, wv, out);
}